// round 1
// baseline (speedup 1.0000x reference)
#include <cuda_runtime.h>

// Problem constants (fixed by the reference: B=16, S=2048, D=768, fp32)
#define B_DIM 16
#define S_DIM 2048
#define D_DIM 768
#define V4    (D_DIM / 4)   // 192 float4 per row

// Segment-mean via binary search on sorted per-row seg ids.
// One CTA per (word slot w, batch b). Each thread owns one float4 column.
// out[b, w, :] = mean over run of positions p with seg[b,p] == w, or zeros.
__global__ __launch_bounds__(V4) void seg_mean_kernel(
    const float* __restrict__ x,    // [B, S, D]
    const int*   __restrict__ seg,  // [B, S] sorted non-decreasing per row
    float*       __restrict__ out)  // [B, S, D]
{
    const int w = blockIdx.x;   // output word slot
    const int b = blockIdx.y;
    const int t = threadIdx.x;  // float4 lane 0..191

    const int* __restrict__ srow = seg + b * S_DIM;

    // lower_bound: first idx with srow[idx] >= w
    int lo = 0, hi = S_DIM;
    while (lo < hi) {
        int m = (lo + hi) >> 1;
        if (__ldg(srow + m) < w) lo = m + 1; else hi = m;
    }
    const int start = lo;
    // upper_bound: first idx with srow[idx] > w
    hi = S_DIM;
    while (lo < hi) {
        int m = (lo + hi) >> 1;
        if (__ldg(srow + m) <= w) lo = m + 1; else hi = m;
    }
    const int cnt = lo - start;

    float4* o = reinterpret_cast<float4*>(
                    out + ((size_t)b * S_DIM + w) * D_DIM) + t;

    if (cnt == 0) {
        *o = make_float4(0.f, 0.f, 0.f, 0.f);
        return;
    }

    const float* xbase = x + ((size_t)b * S_DIM + start) * D_DIM;
    float4 acc = *(reinterpret_cast<const float4*>(xbase) + t);
    for (int i = 1; i < cnt; i++) {
        const float4 v = *(reinterpret_cast<const float4*>(
                              xbase + (size_t)i * D_DIM) + t);
        acc.x += v.x; acc.y += v.y; acc.z += v.z; acc.w += v.w;
    }
    const float inv = 1.0f / (float)cnt;
    acc.x *= inv; acc.y *= inv; acc.z *= inv; acc.w *= inv;
    *o = acc;
}

extern "C" void kernel_launch(void* const* d_in, const int* in_sizes, int n_in,
                              void* d_out, int out_size)
{
    const float* x   = (const float*)d_in[0];  // robert_embed [16,2048,768] f32
    const int*   seg = (const int*)  d_in[1];  // seg_ids      [16,2048]     i32
    float*       out = (float*)d_out;          // [16,2048,768] f32

    dim3 grid(S_DIM, B_DIM);
    seg_mean_kernel<<<grid, V4>>>(x, seg, out);
}